// round 8
// baseline (speedup 1.0000x reference)
#include <cuda_runtime.h>
#include <cstdint>

// RipsH1 edge-length gather — pair-cooperative, U=8 front-batched.
// (R4 schedule — the best measured — with a deeper gather batch.)
//
// Flat distance list, D = e0 + 2*e1:
//   t <  e0 : (ia, ib) = verts0 row t
//   t >= e0 : (ia, ib) = ((int2*)verts1)[t - e0]
//   out[t]  = || pts[ia] - pts[ib] ||      (8-dim)
//
// Floor analysis: 2 random 32B point rows per distance -> ~2.1 L1 wavefronts
// per distance at rt_L1tex_wf ~= 1 cyc/wf; measured kernels sit at ~89% of
// that floor. This round: 16 in-flight gathers/lane (U=8) to keep the l1tex
// wavefront pipe saturated across batch boundaries and halve loop overhead.

static constexpr int DIM_F4   = 2;      // 8 floats = 2 float4
static constexpr int IDX_MASK = 0xFFFF; // N_POINTS = 65536
static constexpr int U        = 8;      // distances per lane-pair
static constexpr int DIST_PER_WARP = 16 * U;  // 128

__global__ __launch_bounds__(256)
void rips_pair_u8_kernel(const float4* __restrict__ pts,
                         const int2* __restrict__ v0,   // e0 rows of 2 i32
                         const int2* __restrict__ v1p,  // verts1 as 2*e1 int2 pairs
                         float* __restrict__ out,
                         int e0, int total) {           // total = e0 + 2*e1
    const int gtid = blockIdx.x * blockDim.x + threadIdx.x;
    const int warp = gtid >> 5;
    const int lane = gtid & 31;
    const int pair = lane >> 1;   // 0..15
    const int h    = lane & 1;    // float4 half owned by this lane

    const int base = warp * DIST_PER_WARP + pair;

    // ---- phase 1: index loads (batched) ----
    int t[U], ia[U], ib[U];
    bool valid[U];
#pragma unroll
    for (int u = 0; u < U; u++) {
        int tt = base + u * 16;
        valid[u] = (tt < total);
        tt = valid[u] ? tt : (total - 1);      // clamp -> safe, converged
        t[u] = tt;
        const int2 p = (tt < e0) ? __ldg(v0 + tt)
                                 : __ldg(v1p + (tt - e0));
        ia[u] = p.x & IDX_MASK;
        ib[u] = p.y & IDX_MASK;
    }

    // ---- phase 2: gathers (batched; 16 independent LDG.128 in flight) ----
    float4 a[U], b[U];
#pragma unroll
    for (int u = 0; u < U; u++) {
        a[u] = __ldg(pts + ia[u] * DIM_F4 + h);
        b[u] = __ldg(pts + ib[u] * DIM_F4 + h);
    }

    // ---- phase 3: math + pair-combine + store ----
#pragma unroll
    for (int u = 0; u < U; u++) {
        float dx, s;
        dx = a[u].x - b[u].x; s = dx * dx;
        dx = a[u].y - b[u].y; s = fmaf(dx, dx, s);
        dx = a[u].z - b[u].z; s = fmaf(dx, dx, s);
        dx = a[u].w - b[u].w; s = fmaf(dx, dx, s);
        s += __shfl_xor_sync(0xFFFFFFFF, s, 1);
        if (valid[u] && h == 0)
            out[t[u]] = sqrtf(s);
    }
}

extern "C" void kernel_launch(void* const* d_in, const int* in_sizes, int n_in,
                              void* d_out, int out_size) {
    const float4* pts = (const float4*)d_in[0];
    const int2*   v0  = (const int2*)d_in[1];
    const int2*   v1p = (const int2*)d_in[2];
    float*        out = (float*)d_out;

    const int e0 = in_sizes[1] / 2;          // verts0 rows
    const int e1 = in_sizes[2] / 4;          // verts1 rows
    const int total = e0 + 2 * e1;           // flat distance count

    const int nwarps  = (total + DIST_PER_WARP - 1) / DIST_PER_WARP;
    const int threads = 256;
    const int blocks  = (nwarps * 32 + threads - 1) / threads;
    rips_pair_u8_kernel<<<blocks, threads>>>(pts, v0, v1p, out, e0, total);
}

// round 9
// speedup vs baseline: 1.0626x; 1.0626x over previous
#include <cuda_runtime.h>
#include <cstdint>

// RipsH1 edge-length gather — FINAL: pair-cooperative, U=4 front-batched
// (best measured schedule, R4) + occupancy cap raised via launch_bounds.
//
// Flat distance list, D = e0 + 2*e1:
//   t <  e0 : (ia, ib) = verts0 row t
//   t >= e0 : (ia, ib) = ((int2*)verts1)[t - e0]
//   out[t]  = || pts[ia] - pts[ib] ||      (8-dim)
//
// Design (evidence from R2-R8 sweeps):
// - 2 lanes per distance, lane h owns float4 half h of each point; the two
//   16B halves share one 32B sector -> 1 L1 wavefront per point instead of 2.
//   (R2->R3: 49.9 -> 39.6us)
// - U=4 distances per lane-pair, index loads then gathers front-batched
//   (8 independent LDG.128 in flight). U-sweep: U=2 37.3, U=4 35.3, U=8 39.7.
// - Kernel runs at ~89% of the structural l1tex floor (~2 random 32B rows
//   per distance @ ~1 cyc/wavefront); occupancy/prefetch/cache-hint variants
//   all landed within noise of this.
// - __launch_bounds__(256, 6): R4 used 41 regs at 56% occ; cap at 42 regs
//   lifts the theoretical ceiling to 75% with zero spill risk.

static constexpr int DIM_F4   = 2;      // 8 floats = 2 float4
static constexpr int IDX_MASK = 0xFFFF; // N_POINTS = 65536
static constexpr int U        = 4;      // distances per lane-pair
static constexpr int DIST_PER_WARP = 16 * U;  // 64

__global__ __launch_bounds__(256, 6)
void rips_pair_u4_kernel(const float4* __restrict__ pts,
                         const int2* __restrict__ v0,   // e0 rows of 2 i32
                         const int2* __restrict__ v1p,  // verts1 as 2*e1 int2 pairs
                         float* __restrict__ out,
                         int e0, int total) {           // total = e0 + 2*e1
    const int gtid = blockIdx.x * blockDim.x + threadIdx.x;
    const int warp = gtid >> 5;
    const int lane = gtid & 31;
    const int pair = lane >> 1;   // 0..15
    const int h    = lane & 1;    // float4 half owned by this lane

    const int base = warp * DIST_PER_WARP + pair;

    // ---- phase 1: index loads (batched) ----
    int t[U], ia[U], ib[U];
    bool valid[U];
#pragma unroll
    for (int u = 0; u < U; u++) {
        int tt = base + u * 16;
        valid[u] = (tt < total);
        tt = valid[u] ? tt : (total - 1);      // clamp -> safe, converged
        t[u] = tt;
        const int2 p = (tt < e0) ? __ldg(v0 + tt)
                                 : __ldg(v1p + (tt - e0));
        ia[u] = p.x & IDX_MASK;
        ib[u] = p.y & IDX_MASK;
    }

    // ---- phase 2: gathers (batched; 8 independent LDG.128 in flight) ----
    float4 a[U], b[U];
#pragma unroll
    for (int u = 0; u < U; u++) {
        a[u] = __ldg(pts + ia[u] * DIM_F4 + h);
        b[u] = __ldg(pts + ib[u] * DIM_F4 + h);
    }

    // ---- phase 3: math + pair-combine + store ----
#pragma unroll
    for (int u = 0; u < U; u++) {
        float dx, s;
        dx = a[u].x - b[u].x; s = dx * dx;
        dx = a[u].y - b[u].y; s = fmaf(dx, dx, s);
        dx = a[u].z - b[u].z; s = fmaf(dx, dx, s);
        dx = a[u].w - b[u].w; s = fmaf(dx, dx, s);
        s += __shfl_xor_sync(0xFFFFFFFF, s, 1);
        if (valid[u] && h == 0)
            out[t[u]] = sqrtf(s);
    }
}

extern "C" void kernel_launch(void* const* d_in, const int* in_sizes, int n_in,
                              void* d_out, int out_size) {
    const float4* pts = (const float4*)d_in[0];
    const int2*   v0  = (const int2*)d_in[1];
    const int2*   v1p = (const int2*)d_in[2];
    float*        out = (float*)d_out;

    const int e0 = in_sizes[1] / 2;          // verts0 rows
    const int e1 = in_sizes[2] / 4;          // verts1 rows
    const int total = e0 + 2 * e1;           // flat distance count

    const int nwarps  = (total + DIST_PER_WARP - 1) / DIST_PER_WARP;
    const int threads = 256;
    const int blocks  = (nwarps * 32 + threads - 1) / threads;
    rips_pair_u4_kernel<<<blocks, threads>>>(pts, v0, v1p, out, e0, total);
}

// round 10
// speedup vs baseline: 1.0764x; 1.0130x over previous
#include <cuda_runtime.h>
#include <cstdint>

// RipsH1 edge-length gather — FINAL (R4 configuration, best measured: 35.3us).
//
// Flat distance list, D = e0 + 2*e1:
//   t <  e0 : (ia, ib) = verts0 row t
//   t >= e0 : (ia, ib) = ((int2*)verts1)[t - e0]
//   out[t]  = || pts[ia] - pts[ib] ||      (8-dim)
// (verts1 row j = [a0,b0,a1,b1]; out layout [deaths ++ dgm1-rowmajor] makes
//  the flat output index equal t exactly.)
//
// Design, with the evidence that selected it (R2-R9 sweeps):
// - 2 lanes per distance: lane h in {0,1} owns float4 half h of each point.
//   The two 16B halves of a 32B-aligned point row share one 32B sector, so a
//   lane-pair's loads coalesce into ONE l1tex wavefront per point (2/distance
//   instead of 4).  R2->R3: 49.9 -> 39.6us.
// - U=4 distances per lane-pair, index loads then gathers front-batched so 8
//   independent LDG.128 are in flight per thread. U-sweep: U=2 37.3us,
//   U=4 35.3us, U=8 39.7us (regs 79 -> occ 33% starves the wavefront pipe).
// - No launch_bounds cap: natural 41 regs / 56% occ. Occupancy sweep
//   (33/56/66/87%) showed zero sensitivity; the reg cap worsened ncu-dur.
// - No .cg/.cs hints: measured neutral (R5, R7).
// - Kernel runs at ~0.89 wf/cyc vs the ~1.0 cyc/wf l1tex cap — ~89% of the
//   structural floor for 2 non-dedupable random 32B gathers per distance.

static constexpr int DIM_F4   = 2;      // 8 floats = 2 float4
static constexpr int IDX_MASK = 0xFFFF; // N_POINTS = 65536 (power of two)
static constexpr int U        = 4;      // distances per lane-pair
static constexpr int DIST_PER_WARP = 16 * U;  // 64

__global__ __launch_bounds__(256)
void rips_pair_u4_kernel(const float4* __restrict__ pts,
                         const int2* __restrict__ v0,   // e0 rows of 2 i32
                         const int2* __restrict__ v1p,  // verts1 as 2*e1 int2 pairs
                         float* __restrict__ out,
                         int e0, int total) {           // total = e0 + 2*e1
    const int gtid = blockIdx.x * blockDim.x + threadIdx.x;
    const int warp = gtid >> 5;
    const int lane = gtid & 31;
    const int pair = lane >> 1;   // 0..15
    const int h    = lane & 1;    // float4 half owned by this lane

    const int base = warp * DIST_PER_WARP + pair;

    // ---- phase 1: index loads (batched) ----
    int t[U], ia[U], ib[U];
    bool valid[U];
#pragma unroll
    for (int u = 0; u < U; u++) {
        int tt = base + u * 16;
        valid[u] = (tt < total);
        tt = valid[u] ? tt : (total - 1);      // clamp -> safe, converged
        t[u] = tt;
        const int2 p = (tt < e0) ? __ldg(v0 + tt)
                                 : __ldg(v1p + (tt - e0));
        ia[u] = p.x & IDX_MASK;
        ib[u] = p.y & IDX_MASK;
    }

    // ---- phase 2: gathers (batched; 8 independent LDG.128 in flight) ----
    float4 a[U], b[U];
#pragma unroll
    for (int u = 0; u < U; u++) {
        a[u] = __ldg(pts + ia[u] * DIM_F4 + h);
        b[u] = __ldg(pts + ib[u] * DIM_F4 + h);
    }

    // ---- phase 3: math + pair-combine + store ----
#pragma unroll
    for (int u = 0; u < U; u++) {
        float dx, s;
        dx = a[u].x - b[u].x; s = dx * dx;
        dx = a[u].y - b[u].y; s = fmaf(dx, dx, s);
        dx = a[u].z - b[u].z; s = fmaf(dx, dx, s);
        dx = a[u].w - b[u].w; s = fmaf(dx, dx, s);
        s += __shfl_xor_sync(0xFFFFFFFF, s, 1);
        if (valid[u] && h == 0)
            out[t[u]] = sqrtf(s);
    }
}

extern "C" void kernel_launch(void* const* d_in, const int* in_sizes, int n_in,
                              void* d_out, int out_size) {
    const float4* pts = (const float4*)d_in[0];
    const int2*   v0  = (const int2*)d_in[1];
    const int2*   v1p = (const int2*)d_in[2];
    float*        out = (float*)d_out;

    const int e0 = in_sizes[1] / 2;          // verts0 rows
    const int e1 = in_sizes[2] / 4;          // verts1 rows
    const int total = e0 + 2 * e1;           // flat distance count

    const int nwarps  = (total + DIST_PER_WARP - 1) / DIST_PER_WARP;
    const int threads = 256;
    const int blocks  = (nwarps * 32 + threads - 1) / threads;
    rips_pair_u4_kernel<<<blocks, threads>>>(pts, v0, v1p, out, e0, total);
}